// round 5
// baseline (speedup 1.0000x reference)
#include <cuda_runtime.h>
#include <math.h>
#include <stdint.h>

#define Bb   32
#define Ss   256
#define Ee   768
#define Hh   512
#define Cc   30
#define IN0v 770
#define Gg   2048
#define SB   (Ss*Bb)          /* 8192 */
#define LSTRIDE (Bb*Ss*Ee)    /* hidden_states layer stride */
#define NCTA_DIR 64

// ---------------- scratch (device globals; no runtime allocation) ------------
__device__ float g_x0[SB*IN0v];        // [S][B][770]  layer-0 input features
__device__ float g_xw[2][SB*Gg];       // [dir][S][B][2048] precomputed input proj
__device__ float g_seq0[SB*1024];      // [S][B][1024] layer-0 output
__device__ float g_seq1[SB*1024];      // [S][B][1024] layer-1 output
__device__ float g_hT[2*2*Hh*Bb];      // [dir][parity][h][b] double-buffered h
__device__ float g_mw[Bb*Ss];          // mean over E per (b,s)
__device__ float g_mp[Bb];             // mean at predicate position per b
__device__ unsigned g_cnt[2];          // per-direction barrier arrive count
__device__ unsigned g_gen[2];          // per-direction barrier generation

// ---------------- feature build ----------------------------------------------
__global__ void feat_mean_kernel(const float* __restrict__ hs)
{
    int bs = blockIdx.x;              // b*Ss + s
    int b = bs / Ss, s = bs % Ss;
    const float* p = hs + ((size_t)b*Ss + s)*Ee;
    size_t xb = ((size_t)s*Bb + b)*IN0v;
    float lsum = 0.f;
    for (int e = threadIdx.x; e < Ee; e += 256){
        float v = (p[e] + p[e+LSTRIDE] + p[e+2*LSTRIDE] + p[e+3*LSTRIDE])*0.25f;
        g_x0[xb + e] = v;
        lsum += v;
    }
    __shared__ float sred[256];
    sred[threadIdx.x] = lsum;
    __syncthreads();
    for (int st = 128; st > 0; st >>= 1){
        if (threadIdx.x < st) sred[threadIdx.x] += sred[threadIdx.x + st];
        __syncthreads();
    }
    if (threadIdx.x == 0) g_mw[bs] = sred[0]*(1.f/768.f);
}

__global__ void pred_kernel(const int* __restrict__ pred)
{
    int b = threadIdx.x;
    if (b >= Bb) return;
    const int* row = pred + b*Ss;
    int best = row[0], idx = 0;
    for (int s = 1; s < Ss; s++){ int v = row[s]; if (v > best){ best = v; idx = s; } }
    g_mp[b] = g_mw[b*Ss + idx];
}

__global__ void fill_kernel(const int* __restrict__ roles)
{
    int t = blockIdx.x*blockDim.x + threadIdx.x;
    if (t >= Bb*Ss) return;
    int b = t / Ss, s = t % Ss;
    int r = roles[t];
    size_t xb = ((size_t)s*Bb + b)*IN0v;
    g_x0[xb + Ee]     = g_mw[t] - g_mp[b];
    g_x0[xb + Ee + 1] = (r != 0 && r != -100) ? 1.f : 0.f;
}

// ---------------- input-projection SGEMM  C = A * W^T + (b1+b2) --------------
// A: [M=8192, K] row-major (src selected inside), W: [N=2048, K] row-major.
__global__ __launch_bounds__(256) void sgemm_bias(
    int srcSel, const float* __restrict__ W,
    const float* __restrict__ b1, const float* __restrict__ b2,
    int dstDir, int K)
{
    const float* A = srcSel ? g_seq0 : g_x0;
    float* Cmat = g_xw[dstDir];
    const int N = Gg;
    __shared__ float As[8][128];
    __shared__ float Wsm[8][128];
    int m0 = blockIdx.y*128, n0 = blockIdx.x*128;
    int tid = threadIdx.x;
    int tx = tid & 15, ty = tid >> 4;
    float acc[8][8];
#pragma unroll
    for (int i=0;i<8;i++)
#pragma unroll
        for (int j=0;j<8;j++) acc[i][j] = 0.f;

    for (int k0 = 0; k0 < K; k0 += 8){
#pragma unroll
        for (int i = 0; i < 4; i++){
            int idx = tid + i*256;
            int kk = idx & 7, mm = idx >> 3;
            int gk = k0 + kk;
            float av = 0.f, wv = 0.f;
            if (gk < K){
                av = A[(size_t)(m0+mm)*K + gk];
                wv = W[(size_t)(n0+mm)*K + gk];
            }
            As[kk][mm] = av;
            Wsm[kk][mm] = wv;
        }
        __syncthreads();
#pragma unroll
        for (int kk = 0; kk < 8; kk++){
            float a[8], w[8];
#pragma unroll
            for (int i=0;i<8;i++) a[i] = As[kk][ty*8+i];
#pragma unroll
            for (int j=0;j<8;j++) w[j] = Wsm[kk][tx*8+j];
#pragma unroll
            for (int i=0;i<8;i++)
#pragma unroll
                for (int j=0;j<8;j++)
                    acc[i][j] = fmaf(a[i], w[j], acc[i][j]);
        }
        __syncthreads();
    }
#pragma unroll
    for (int i=0;i<8;i++){
        int m = m0 + ty*8 + i;
#pragma unroll
        for (int j=0;j<8;j++){
            int n = n0 + tx*8 + j;
            Cmat[(size_t)m*N + n] = acc[i][j] + b1[n] + b2[n];
        }
    }
}

// ---------------- persistent bidirectional LSTM layer ------------------------
__device__ __forceinline__ float sigf(float x){ return 1.f/(1.f + expf(-x)); }

__device__ __forceinline__ void grid_bar(int dir, unsigned* s_gen)
{
    __syncthreads();
    if (threadIdx.x == 0){
        __threadfence();
        unsigned g0 = *s_gen;
        if (atomicAdd(&g_cnt[dir], 1u) == NCTA_DIR - 1u){
            g_cnt[dir] = 0u;
            __threadfence();
            atomicAdd(&g_gen[dir], 1u);
        } else {
            while (atomicAdd(&g_gen[dir], 0u) == g0) { __nanosleep(64); }
        }
        __threadfence();
        *s_gen = g0 + 1u;
    }
    __syncthreads();
}

// grid = 128 CTAs (64 per direction), 256 threads, dynamic smem 147968 B.
// CTA owns 8 h-columns (all 4 gates) for all 32 batches; Whh slice persists in SMEM.
__global__ __launch_bounds__(256,1) void lstm_layer_kernel(
    const float* __restrict__ Whh_f, const float* __restrict__ Whh_b, int layer)
{
    extern __shared__ float sm[];
    float* W_s  = sm;                    // [512][32] transposed Whh slice  (64KB)
    float* hp_s = sm + 512*32;           // [512][32] h_prev transposed     (64KB)
    float* red  = sm + 2*512*32;         // [4][32][33] partials/gates      (~16.5KB)
    __shared__ unsigned s_gen;

    int dir = blockIdx.x >> 6;
    int cid = blockIdx.x & 63;
    int hc0 = cid * 8;
    int tid = threadIdx.x;
    const float* Whh = dir ? Whh_b : Whh_f;
    const float* xw  = g_xw[dir];
    float* outseq = layer ? g_seq1 : g_seq0;

    if (tid == 0) s_gen = g_gen[dir];

    // Load Whh slice transposed: W_s[k][q*8+j] = Whh[q*512 + hc0 + j][k]
    for (int idx = tid; idx < 512*32; idx += 256){
        int col = idx & 31, k = idx >> 5;
        int q = col >> 3, j = col & 7;
        W_s[k*32 + col] = Whh[(size_t)(q*512 + hc0 + j)*512 + k];
    }
    // Zero parity-0 h buffer for the columns this CTA owns
    {
        int j = tid >> 5, b = tid & 31;
        g_hT[(dir*2 + 0)*Hh*Bb + (hc0+j)*Bb + b] = 0.f;
    }
    float c_reg = 0.f;                   // cell state: thread (jj,bb) owns c[hc0+jj][bb]
    int jj = tid >> 5, bbn = tid & 31;

    int kg = tid >> 6;                   // k-split group (4 groups of 128 k each)
    int t2 = tid & 63;
    int bq = (t2 & 7) * 4;               // batch quad
    int gq = (t2 >> 3) * 4;              // gate-col quad

    grid_bar(dir, &s_gen);

    for (int t = 0; t < Ss; t++){
        int s = dir ? (Ss - 1 - t) : t;
        const float* hsrc = g_hT + (dir*2 + (t & 1))*Hh*Bb;
        for (int idx = tid; idx < 512*32; idx += 256)
            hp_s[idx] = hsrc[idx];
        __syncthreads();

        float acc[4][4];
#pragma unroll
        for (int i=0;i<4;i++)
#pragma unroll
            for (int j=0;j<4;j++) acc[i][j] = 0.f;

        const float* hpk = hp_s + kg*128*32;
        const float* wpk = W_s  + kg*128*32;
#pragma unroll 8
        for (int k = 0; k < 128; k++){
            float4 hv = *reinterpret_cast<const float4*>(hpk + (k<<5) + bq);
            float4 wv = *reinterpret_cast<const float4*>(wpk + (k<<5) + gq);
            acc[0][0]=fmaf(wv.x,hv.x,acc[0][0]); acc[0][1]=fmaf(wv.x,hv.y,acc[0][1]);
            acc[0][2]=fmaf(wv.x,hv.z,acc[0][2]); acc[0][3]=fmaf(wv.x,hv.w,acc[0][3]);
            acc[1][0]=fmaf(wv.y,hv.x,acc[1][0]); acc[1][1]=fmaf(wv.y,hv.y,acc[1][1]);
            acc[1][2]=fmaf(wv.y,hv.z,acc[1][2]); acc[1][3]=fmaf(wv.y,hv.w,acc[1][3]);
            acc[2][0]=fmaf(wv.z,hv.x,acc[2][0]); acc[2][1]=fmaf(wv.z,hv.y,acc[2][1]);
            acc[2][2]=fmaf(wv.z,hv.z,acc[2][2]); acc[2][3]=fmaf(wv.z,hv.w,acc[2][3]);
            acc[3][0]=fmaf(wv.w,hv.x,acc[3][0]); acc[3][1]=fmaf(wv.w,hv.y,acc[3][1]);
            acc[3][2]=fmaf(wv.w,hv.z,acc[3][2]); acc[3][3]=fmaf(wv.w,hv.w,acc[3][3]);
        }
#pragma unroll
        for (int gi=0; gi<4; gi++)
#pragma unroll
            for (int bi=0; bi<4; bi++)
                red[kg*1056 + (gq+gi)*33 + (bq+bi)] = acc[gi][bi];
        __syncthreads();

        // reduce k-splits + add precomputed input projection -> gate preacts
        const float* xwt = xw + (size_t)s*Bb*Gg;
#pragma unroll
        for (int idx = tid; idx < 1024; idx += 256){
            int bI = idx >> 5, col = idx & 31;
            int q = col >> 3, j2 = col & 7;
            float v = red[col*33 + bI] + red[1056 + col*33 + bI]
                    + red[2112 + col*33 + bI] + red[3168 + col*33 + bI];
            v += xwt[(size_t)bI*Gg + q*512 + hc0 + j2];
            red[col*33 + bI] = v;
        }
        __syncthreads();

        // activations + state update (gate cols: i=j, f=8+j, g=16+j, o=24+j)
        float iv = red[( 0 + jj)*33 + bbn];
        float fv = red[( 8 + jj)*33 + bbn];
        float gv = red[(16 + jj)*33 + bbn];
        float ov = red[(24 + jj)*33 + bbn];
        float cnew = sigf(fv)*c_reg + sigf(iv)*tanhf(gv);
        float hnew = sigf(ov)*tanhf(cnew);
        c_reg = cnew;
        g_hT[(dir*2 + ((t+1)&1))*Hh*Bb + (hc0+jj)*Bb + bbn] = hnew;
        outseq[((size_t)s*Bb + bbn)*1024 + dir*512 + hc0 + jj] = hnew;

        grid_bar(dir, &s_gen);
    }
}

// ---------------- output projection [8192,1024] x [1024,30] ------------------
__global__ void out_proj_kernel(const float* __restrict__ Wout,
                                const float* __restrict__ bout,
                                float* __restrict__ out)
{
    int gw = (blockIdx.x*blockDim.x + threadIdx.x) >> 5;   // one warp per (s,b)
    int lane = threadIdx.x & 31;
    if (gw >= SB) return;
    const float* row = g_seq1 + (size_t)gw*1024;
    float xv[32];
#pragma unroll
    for (int i=0;i<32;i++) xv[i] = row[lane + 32*i];
    int s = gw >> 5, b = gw & 31;
    float* orow = out + ((size_t)b*Ss + s)*Cc;
    for (int c = 0; c < Cc; c++){
        const float* w = Wout + c*1024;
        float acc = 0.f;
#pragma unroll
        for (int i=0;i<32;i++) acc = fmaf(xv[i], w[lane + 32*i], acc);
#pragma unroll
        for (int off=16; off; off>>=1) acc += __shfl_xor_sync(0xffffffffu, acc, off);
        if (lane == 0) orow[c] = acc + bout[c];
    }
}

// ---------------- launch ------------------------------------------------------
extern "C" void kernel_launch(void* const* d_in, const int* in_sizes, int n_in,
                              void* d_out, int out_size)
{
    const float* hs     = (const float*)d_in[0];
    const int*   roles  = (const int*)  d_in[1];
    const int*   preds  = (const int*)  d_in[2];
    const float* Wih0f  = (const float*)d_in[3];
    const float* Whh0f  = (const float*)d_in[4];
    const float* bih0f  = (const float*)d_in[5];
    const float* bhh0f  = (const float*)d_in[6];
    const float* Wih0b  = (const float*)d_in[7];
    const float* Whh0b  = (const float*)d_in[8];
    const float* bih0b  = (const float*)d_in[9];
    const float* bhh0b  = (const float*)d_in[10];
    const float* Wih1f  = (const float*)d_in[11];
    const float* Whh1f  = (const float*)d_in[12];
    const float* bih1f  = (const float*)d_in[13];
    const float* bhh1f  = (const float*)d_in[14];
    const float* Wih1b  = (const float*)d_in[15];
    const float* Whh1b  = (const float*)d_in[16];
    const float* bih1b  = (const float*)d_in[17];
    const float* bhh1b  = (const float*)d_in[18];
    const float* Wout   = (const float*)d_in[19];
    const float* bout   = (const float*)d_in[20];
    float* out = (float*)d_out;

    const size_t lsm = (2*512*32 + 4*1056) * sizeof(float);   // 147968
    cudaFuncSetAttribute(lstm_layer_kernel,
                         cudaFuncAttributeMaxDynamicSharedMemorySize, (int)lsm);

    feat_mean_kernel<<<SB, 256>>>(hs);
    pred_kernel<<<1, 32>>>(preds);
    fill_kernel<<<(Bb*Ss + 255)/256, 256>>>(roles);

    dim3 gproj(Gg/128, SB/128);
    sgemm_bias<<<gproj, 256>>>(0, Wih0f, bih0f, bhh0f, 0, IN0v);
    sgemm_bias<<<gproj, 256>>>(0, Wih0b, bih0b, bhh0b, 1, IN0v);
    lstm_layer_kernel<<<128, 256, lsm>>>(Whh0f, Whh0b, 0);

    sgemm_bias<<<gproj, 256>>>(1, Wih1f, bih1f, bhh1f, 0, 1024);
    sgemm_bias<<<gproj, 256>>>(1, Wih1b, bih1b, bhh1b, 1, 1024);
    lstm_layer_kernel<<<128, 256, lsm>>>(Whh1f, Whh1b, 1);

    out_proj_kernel<<<(SB*32 + 255)/256, 256>>>(Wout, bout, out);
}